// round 1
// baseline (speedup 1.0000x reference)
#include <cuda_runtime.h>
#include <cstdint>

#define T_SEQ 2048
#define NB    64
#define DIN   256
#define NH    256

// scratch: precomputed input projection xw[t][b][h]  (128 MB, static — no allocs)
__device__ float g_xw[(size_t)T_SEQ * NB * NH];

// ---------------- packed fp32x2 helpers (sm_100+) ----------------
__device__ __forceinline__ unsigned long long fma2(unsigned long long a,
                                                   unsigned long long b,
                                                   unsigned long long c) {
    unsigned long long d;
    asm("fma.rn.f32x2 %0, %1, %2, %3;" : "=l"(d) : "l"(a), "l"(b), "l"(c));
    return d;
}
__device__ __forceinline__ float f2sum(unsigned long long v) {
    float lo, hi;
    asm("mov.b64 {%0, %1}, %2;" : "=f"(lo), "=f"(hi) : "l"(v));
    return lo + hi;
}
__device__ __forceinline__ uint32_t smem_u32(const void* p) {
    uint32_t a;
    asm("{.reg .u64 t; cvta.to.shared.u64 t, %1; cvt.u32.u64 %0, t;}"
        : "=r"(a) : "l"(p));
    return a;
}
__device__ __forceinline__ void cluster_sync_() {
    asm volatile("barrier.cluster.arrive.aligned;\n\t"
                 "barrier.cluster.wait.aligned;" ::: "memory");
}

// =================================================================
// Kernel 1: input projection  g_xw[row][j] = x[row]·w_ih[j] + b_ih[j] + b_hh[j]
//   rows = t*NB + b  (131072 rows), j in [0,256)
//   grid: (1024 row-chunks of 128, 2 column halves). 256 threads.
//   Weights register-resident: thread owns 2 output cols x 64-k slice.
// =================================================================
__global__ void __launch_bounds__(256, 1)
xw_kernel(const float* __restrict__ x,
          const float* __restrict__ w_ih,
          const float* __restrict__ b_ih,
          const float* __restrict__ b_hh) {
    __shared__ __align__(16) float xs[8][256];   // 8 staged rows
    __shared__ float pbuf[8 * 512];              // 8 rows x 4 kg x 128 jl

    const int tid  = threadIdx.x;
    const int w    = tid >> 5;
    const int lane = tid & 31;
    const int kg   = w >> 1;                    // k-slice 0..3 (warp-uniform)
    const int og   = ((w & 1) << 5) | lane;     // output group 0..63
    const int half = blockIdx.y;
    const int rowbase0 = blockIdx.x * 128;

    // register-resident weights: cols j0=half*128+og, j1=j0+64, k in [64*kg, 64*kg+64)
    unsigned long long wa[32], wb[32];
    {
        const int j0 = half * 128 + og, j1 = j0 + 64;
        const unsigned long long* p0 =
            (const unsigned long long*)(w_ih + (size_t)j0 * DIN + kg * 64);
        const unsigned long long* p1 =
            (const unsigned long long*)(w_ih + (size_t)j1 * DIN + kg * 64);
#pragma unroll
        for (int i = 0; i < 32; i++) { wa[i] = p0[i]; wb[i] = p1[i]; }
    }
    float bias = 0.f;
    if (tid < 128) bias = b_ih[half * 128 + tid] + b_hh[half * 128 + tid];

    const float4* xg = (const float4*)x;
    {   // stage first 8 rows
        int q = tid, r = q >> 6, c4 = q & 63;
        ((float4*)xs)[q]       = xg[(size_t)(rowbase0 + r) * 64 + c4];
        ((float4*)xs)[q + 256] = xg[(size_t)(rowbase0 + 4 + r) * 64 + c4];
    }
    __syncthreads();

    for (int it = 0; it < 16; it++) {
        const int rowbase = rowbase0 + it * 8;
        float4 n0, n1;
        if (it < 15) {   // prefetch next 8 rows into regs
            int q = tid, r = q >> 6, c4 = q & 63;
            int nrb = rowbase + 8;
            n0 = xg[(size_t)(nrb + r) * 64 + c4];
            n1 = xg[(size_t)(nrb + 4 + r) * 64 + c4];
        }
        // ---- phase A: 8 rows x 2 outputs x 64 k  (512 FFMA2/thread) ----
        unsigned long long acc[8][2];
#pragma unroll
        for (int r = 0; r < 8; r++) { acc[r][0] = 0ull; acc[r][1] = 0ull; }
#pragma unroll
        for (int r = 0; r < 8; r++) {
            const ulonglong2* xp = (const ulonglong2*)&xs[r][kg * 64];
#pragma unroll
            for (int i = 0; i < 16; i++) {
                ulonglong2 hv = xp[i];
                acc[r][0] = fma2(wa[2 * i],     hv.x, acc[r][0]);
                acc[r][0] = fma2(wa[2 * i + 1], hv.y, acc[r][0]);
                acc[r][1] = fma2(wb[2 * i],     hv.x, acc[r][1]);
                acc[r][1] = fma2(wb[2 * i + 1], hv.y, acc[r][1]);
            }
        }
#pragma unroll
        for (int r = 0; r < 8; r++) {
            pbuf[r * 512 + kg * 128 + og]      = f2sum(acc[r][0]);
            pbuf[r * 512 + kg * 128 + og + 64] = f2sum(acc[r][1]);
        }
        __syncthreads();
        if (it < 15) {   // stage next rows (reads of xs are done)
            int q = tid;
            ((float4*)xs)[q]       = n0;
            ((float4*)xs)[q + 256] = n1;
        }
        // ---- phase B: reduce 4 partials, add bias, store ----
        if (tid < 128) {
#pragma unroll
            for (int r = 0; r < 8; r++) {
                float s = pbuf[r * 512 + tid] + pbuf[r * 512 + 128 + tid] +
                          pbuf[r * 512 + 256 + tid] + pbuf[r * 512 + 384 + tid] + bias;
                g_xw[(size_t)(rowbase + r) * NH + half * 128 + tid] = s;
            }
        }
        __syncthreads();
    }
}

// =================================================================
// Kernel 2: persistent recurrence.
//   64 clusters (one per batch row) x 2 CTAs. CTA c owns outputs [c*128, c*128+128).
//   w_hh half register-resident per CTA. h double-buffered in SMEM; each step the
//   new half is pushed to the peer via st.shared::cluster, cluster barrier syncs.
// =================================================================
__global__ void __launch_bounds__(256, 1) __cluster_dims__(2, 1, 1)
rnn_kernel(const float* __restrict__ w_hh, float* __restrict__ out) {
    __shared__ __align__(16) float hbuf[2][256];
    __shared__ float pbuf[512];

    const int tid  = threadIdx.x;
    const int w    = tid >> 5;
    const int lane = tid & 31;
    const int kg   = w >> 1;                   // warp-uniform k-slice
    const int og   = ((w & 1) << 5) | lane;
    const int b    = blockIdx.x >> 1;          // batch row
    const int c    = blockIdx.x & 1;           // cluster rank
    const int peer = c ^ 1;

    // register-resident w_hh half: rows j0=c*128+og, j1=j0+64, k-slice kg
    unsigned long long wa[32], wb[32];
    {
        const int j0 = c * 128 + og, j1 = j0 + 64;
        const unsigned long long* p0 =
            (const unsigned long long*)(w_hh + (size_t)j0 * NH + kg * 64);
        const unsigned long long* p1 =
            (const unsigned long long*)(w_hh + (size_t)j1 * NH + kg * 64);
#pragma unroll
        for (int i = 0; i < 32; i++) { wa[i] = p0[i]; wb[i] = p1[i]; }
    }

    hbuf[0][tid] = 0.f;                        // h0 = 0 (all 256 entries)
    const int j = c * 128 + (tid & 127);       // this thread's output col (tid<128)
    const uint32_t haddr0 = smem_u32(&hbuf[0][j]);
    const uint32_t haddr1 = smem_u32(&hbuf[1][j]);

    float xw_cur = 0.f;
    if (tid < 128) xw_cur = __ldg(&g_xw[(size_t)b * NH + j]);   // step 0

    cluster_sync_();   // both CTAs' hbuf[0] ready

    int p = 0;
    for (int s = 0; s < T_SEQ; s++) {
        float xw_nxt = 0.f;
        if (tid < 128 && s + 1 < T_SEQ)
            xw_nxt = __ldg(&g_xw[((size_t)(s + 1) * NB + b) * NH + j]);

        // ---- recurrence GEMV slice: 2 outputs x 64 k (64 FFMA2) ----
        const ulonglong2* hp = (const ulonglong2*)&hbuf[p][kg * 64];
        unsigned long long a0 = 0ull, a1 = 0ull;
#pragma unroll
        for (int i = 0; i < 16; i++) {
            ulonglong2 hv = hp[i];               // warp-uniform broadcast LDS.128
            a0 = fma2(wa[2 * i],     hv.x, a0);
            a0 = fma2(wa[2 * i + 1], hv.y, a0);
            a1 = fma2(wb[2 * i],     hv.x, a1);
            a1 = fma2(wb[2 * i + 1], hv.y, a1);
        }
        pbuf[kg * 128 + og]      = f2sum(a0);
        pbuf[kg * 128 + og + 64] = f2sum(a1);
        __syncthreads();

        if (tid < 128) {
            float sum = pbuf[tid] + pbuf[128 + tid] + pbuf[256 + tid] +
                        pbuf[384 + tid] + xw_cur;
            float v = tanhf(sum);
            hbuf[p ^ 1][j] = v;                              // local copy
            uint32_t ra = p ? haddr0 : haddr1;               // peer copy (push)
            asm volatile(
                "{.reg .b32 rr; mapa.shared::cluster.u32 rr, %0, %1; "
                "st.shared::cluster.f32 [rr], %2;}"
                :: "r"(ra), "r"(peer), "f"(v) : "memory");
            out[((size_t)s * NB + b) * NH + j] = v;
            xw_cur = xw_nxt;
        }
        cluster_sync_();   // peer half visible; pbuf reads done
        p ^= 1;
    }
}

// =================================================================
extern "C" void kernel_launch(void* const* d_in, const int* in_sizes, int n_in,
                              void* d_out, int out_size) {
    const float* x    = (const float*)d_in[0];
    const float* w_ih = (const float*)d_in[1];
    const float* w_hh = (const float*)d_in[2];
    const float* b_ih = (const float*)d_in[3];
    const float* b_hh = (const float*)d_in[4];
    float* out = (float*)d_out;

    dim3 g1(1024, 2);
    xw_kernel<<<g1, 256>>>(x, w_ih, b_ih, b_hh);
    rnn_kernel<<<128, 256>>>(w_hh, out);
}